// round 4
// baseline (speedup 1.0000x reference)
#include <cuda_runtime.h>
#include <math.h>

#define S_TXT   512
#define S_IMG   2048
#define S_TOT   2560
#define DM      1536
#define NH      24
#define DH      64
#define SM_SCALE 0.125f

// Scratch (device globals: allocation-free rule)
__device__ __align__(16) float g_q[(size_t)NH * S_TOT * DH];
__device__ __align__(16) float g_k[(size_t)NH * S_TOT * DH];
__device__ __align__(16) float g_v[(size_t)NH * S_TOT * DH];
__device__ __align__(16) float g_o[(size_t)S_TOT * DM];

// ---------------------------------------------------------------------------
// Kernel 1: fused QKV projection (+bias, +RMSNorm(q,k), +RoPE(q,k))
// C[s, 0:1536]=Q, [1536:3072]=K, [3072:4608]=V ; rows <512 use encoder stream.
// 64x64 tiles, 256 threads, 4x4 microtile.
// ---------------------------------------------------------------------------
__global__ __launch_bounds__(256) void qkv_kernel(
    const float* __restrict__ hid, const float* __restrict__ enc,
    const float* __restrict__ rope_cos, const float* __restrict__ rope_sin,
    const float* __restrict__ Wq,  const float* __restrict__ bq,
    const float* __restrict__ Wk,  const float* __restrict__ bk,
    const float* __restrict__ Wv,  const float* __restrict__ bv,
    const float* __restrict__ Waq, const float* __restrict__ baq,
    const float* __restrict__ Wak, const float* __restrict__ bak,
    const float* __restrict__ Wav, const float* __restrict__ bav,
    const float* __restrict__ gq,  const float* __restrict__ gk,
    const float* __restrict__ gaq, const float* __restrict__ gak)
{
    __shared__ __align__(16) float As[16][68];   // [k][row]
    __shared__ __align__(16) float Bs[16][68];   // [k][col]

    const int tx = threadIdx.x, ty = threadIdx.y;
    const int t  = ty * 16 + tx;
    const int col0 = blockIdx.x * 64;
    const int row0 = blockIdx.y * 64;
    const int which = col0 / DM;               // 0=q,1=k,2=v
    const int fcol0 = col0 - which * DM;       // feature col within projection
    const bool is_enc = (row0 < S_TXT);

    const float* X = is_enc ? enc : hid;
    const int xrow0 = is_enc ? row0 : (row0 - S_TXT);

    const float* W; const float* bias;
    if (which == 0)      { W = is_enc ? Waq : Wq; bias = is_enc ? baq : bq; }
    else if (which == 1) { W = is_enc ? Wak : Wk; bias = is_enc ? bak : bk; }
    else                 { W = is_enc ? Wav : Wv; bias = is_enc ? bav : bv; }

    const int lr = t >> 2;   // 0..63 tile row/col for loads
    const int lq = t & 3;    // which float4 of the 16-wide k chunk

    float acc[4][4];
    #pragma unroll
    for (int i = 0; i < 4; i++)
        #pragma unroll
        for (int j = 0; j < 4; j++) acc[i][j] = 0.f;

    const float* Ap = X + (size_t)(xrow0 + lr) * DM + lq * 4;
    const float* Bp = W + (size_t)(fcol0 + lr) * DM + lq * 4;

    for (int k0 = 0; k0 < DM; k0 += 16) {
        float4 a4 = *(const float4*)(Ap + k0);
        float4 b4 = *(const float4*)(Bp + k0);
        As[lq*4+0][lr] = a4.x; As[lq*4+1][lr] = a4.y;
        As[lq*4+2][lr] = a4.z; As[lq*4+3][lr] = a4.w;
        Bs[lq*4+0][lr] = b4.x; Bs[lq*4+1][lr] = b4.y;
        Bs[lq*4+2][lr] = b4.z; Bs[lq*4+3][lr] = b4.w;
        __syncthreads();
        #pragma unroll
        for (int kk = 0; kk < 16; kk++) {
            float4 av  = *(const float4*)&As[kk][ty*4];
            float4 bv4 = *(const float4*)&Bs[kk][tx*4];
            const float ar[4] = {av.x, av.y, av.z, av.w};
            const float br[4] = {bv4.x, bv4.y, bv4.z, bv4.w};
            #pragma unroll
            for (int i = 0; i < 4; i++)
                #pragma unroll
                for (int j = 0; j < 4; j++)
                    acc[i][j] = fmaf(ar[i], br[j], acc[i][j]);
        }
        __syncthreads();
    }

    const int head = fcol0 >> 6;     // tile spans exactly one head
    const int d0 = tx * 4;
    float bb[4];
    #pragma unroll
    for (int j = 0; j < 4; j++) bb[j] = bias[fcol0 + d0 + j];

    if (which == 2) {
        #pragma unroll
        for (int i = 0; i < 4; i++) {
            int s = row0 + ty * 4 + i;
            float4 o;
            o.x = acc[i][0] + bb[0]; o.y = acc[i][1] + bb[1];
            o.z = acc[i][2] + bb[2]; o.w = acc[i][3] + bb[3];
            *(float4*)&g_v[((size_t)head * S_TOT + s) * DH + d0] = o;
        }
    } else {
        const float* gvec = (which == 0) ? (is_enc ? gaq : gq)
                                         : (is_enc ? gak : gk);
        float gg[4];
        #pragma unroll
        for (int j = 0; j < 4; j++) gg[j] = gvec[d0 + j];
        float* OUT = (which == 0) ? g_q : g_k;
        #pragma unroll
        for (int i = 0; i < 4; i++) {
            int s = row0 + ty * 4 + i;
            float x[4]; float ssq = 0.f;
            #pragma unroll
            for (int j = 0; j < 4; j++) {
                x[j] = acc[i][j] + bb[j];
                ssq = fmaf(x[j], x[j], ssq);
            }
            // reduce over the 16 tx lanes owning this row (half-warp = fixed ty)
            #pragma unroll
            for (int m = 1; m < 16; m <<= 1)
                ssq += __shfl_xor_sync(0xffffffffu, ssq, m);
            float rn = rsqrtf(ssq * (1.0f / DH) + 1e-6f);
            #pragma unroll
            for (int j = 0; j < 4; j++) x[j] *= rn * gg[j];
            // RoPE: pairs (d0,d0+1),(d0+2,d0+3) are thread-local
            const float* cp = rope_cos + (size_t)s * DH + d0;
            const float* sp = rope_sin + (size_t)s * DH + d0;
            float4 o;
            o.x = x[0]*cp[0] - x[1]*sp[0];
            o.y = x[1]*cp[1] + x[0]*sp[1];
            o.z = x[2]*cp[2] - x[3]*sp[2];
            o.w = x[3]*cp[3] + x[2]*sp[3];
            *(float4*)&OUT[((size_t)head * S_TOT + s) * DH + d0] = o;
        }
    }
}

// ---------------------------------------------------------------------------
// Kernel 2: flash attention. grid = (40 q-tiles, 24 heads), 256 threads.
// Bq = Bk = 64, online softmax, fp32 throughout.
// ---------------------------------------------------------------------------
__global__ __launch_bounds__(256) void attn_kernel()
{
    extern __shared__ __align__(16) float sm[];
    float* Qs = sm;              // [d][row]  64x68
    float* Ks = Qs + 64 * 68;    // [d][col]  64x68
    float* Vs = Ks + 64 * 68;    // [kr][d]   64x68
    float* Ps = Vs + 64 * 68;    // [row][col]64x68

    const int h  = blockIdx.y;
    const int q0 = blockIdx.x * 64;
    const int tx = threadIdx.x, ty = threadIdx.y;
    const int t  = ty * 16 + tx;

    const float* Qg = g_q + (size_t)h * S_TOT * DH;
    const float* Kg = g_k + (size_t)h * S_TOT * DH;
    const float* Vg = g_v + (size_t)h * S_TOT * DH;

    // load Q tile transposed [d][row]
    #pragma unroll
    for (int ii = 0; ii < 4; ii++) {
        int idx = ii * 256 + t;
        int r = idx >> 4, qd = idx & 15;
        float4 v = *(const float4*)(Qg + (size_t)(q0 + r) * DH + qd * 4);
        Qs[(qd*4+0)*68 + r] = v.x;
        Qs[(qd*4+1)*68 + r] = v.y;
        Qs[(qd*4+2)*68 + r] = v.z;
        Qs[(qd*4+3)*68 + r] = v.w;
    }

    float m_[4], l_[4], o_[4][4];
    #pragma unroll
    for (int i = 0; i < 4; i++) {
        m_[i] = -1e30f; l_[i] = 0.f;
        #pragma unroll
        for (int j = 0; j < 4; j++) o_[i][j] = 0.f;
    }

    for (int k0 = 0; k0 < S_TOT; k0 += 64) {
        __syncthreads();   // prior iter done with Ks/Vs/Ps (and initial Qs visible)
        #pragma unroll
        for (int ii = 0; ii < 4; ii++) {
            int idx = ii * 256 + t;
            int r = idx >> 4, qd = idx & 15;
            float4 kv = *(const float4*)(Kg + (size_t)(k0 + r) * DH + qd * 4);
            Ks[(qd*4+0)*68 + r] = kv.x;
            Ks[(qd*4+1)*68 + r] = kv.y;
            Ks[(qd*4+2)*68 + r] = kv.z;
            Ks[(qd*4+3)*68 + r] = kv.w;
            float4 vv = *(const float4*)(Vg + (size_t)(k0 + r) * DH + qd * 4);
            *(float4*)&Vs[r*68 + qd*4] = vv;
        }
        __syncthreads();

        float sa[4][4];
        #pragma unroll
        for (int i = 0; i < 4; i++)
            #pragma unroll
            for (int j = 0; j < 4; j++) sa[i][j] = 0.f;

        #pragma unroll 8
        for (int d = 0; d < 64; d++) {
            float4 a = *(const float4*)&Qs[d*68 + ty*4];
            float4 b = *(const float4*)&Ks[d*68 + tx*4];
            const float ar[4] = {a.x, a.y, a.z, a.w};
            const float br[4] = {b.x, b.y, b.z, b.w};
            #pragma unroll
            for (int i = 0; i < 4; i++)
                #pragma unroll
                for (int j = 0; j < 4; j++)
                    sa[i][j] = fmaf(ar[i], br[j], sa[i][j]);
        }

        #pragma unroll
        for (int i = 0; i < 4; i++) {
            float s0 = sa[i][0]*SM_SCALE, s1 = sa[i][1]*SM_SCALE;
            float s2 = sa[i][2]*SM_SCALE, s3 = sa[i][3]*SM_SCALE;
            float mx = fmaxf(fmaxf(s0, s1), fmaxf(s2, s3));
            #pragma unroll
            for (int m = 1; m < 16; m <<= 1)
                mx = fmaxf(mx, __shfl_xor_sync(0xffffffffu, mx, m));
            float mn = fmaxf(m_[i], mx);
            float alpha = __expf(m_[i] - mn);
            float p0 = __expf(s0 - mn), p1 = __expf(s1 - mn);
            float p2 = __expf(s2 - mn), p3 = __expf(s3 - mn);
            float rs = (p0 + p1) + (p2 + p3);
            #pragma unroll
            for (int m = 1; m < 16; m <<= 1)
                rs += __shfl_xor_sync(0xffffffffu, rs, m);
            l_[i] = l_[i] * alpha + rs;
            m_[i] = mn;
            #pragma unroll
            for (int j = 0; j < 4; j++) o_[i][j] *= alpha;
            float4 pp; pp.x = p0; pp.y = p1; pp.z = p2; pp.w = p3;
            *(float4*)&Ps[(ty*4+i)*68 + tx*4] = pp;
        }
        __syncthreads();

        #pragma unroll 4
        for (int jj = 0; jj < 64; jj += 4) {
            float pr[4][4];
            #pragma unroll
            for (int i = 0; i < 4; i++) {
                float4 pv = *(const float4*)&Ps[(ty*4+i)*68 + jj];
                pr[i][0] = pv.x; pr[i][1] = pv.y; pr[i][2] = pv.z; pr[i][3] = pv.w;
            }
            #pragma unroll
            for (int u = 0; u < 4; u++) {
                float4 vv = *(const float4*)&Vs[(jj+u)*68 + tx*4];
                const float vr[4] = {vv.x, vv.y, vv.z, vv.w};
                #pragma unroll
                for (int i = 0; i < 4; i++)
                    #pragma unroll
                    for (int j = 0; j < 4; j++)
                        o_[i][j] = fmaf(pr[i][u], vr[j], o_[i][j]);
            }
        }
    }

    #pragma unroll
    for (int i = 0; i < 4; i++) {
        float inv = 1.0f / l_[i];
        int s = q0 + ty * 4 + i;
        float4 o;
        o.x = o_[i][0]*inv; o.y = o_[i][1]*inv;
        o.z = o_[i][2]*inv; o.w = o_[i][3]*inv;
        *(float4*)&g_o[(size_t)s * DM + h * DH + tx * 4] = o;
    }
}

// ---------------------------------------------------------------------------
// Kernel 3: output projection, stream-dependent weights + output reorder.
// out[0 : 2048*1536]   = img tokens (attn rows 512..2559) @ Wo^T + bo
// out[2048*1536 : end] = enc tokens (attn rows 0..511)    @ Wao^T + bao
// ---------------------------------------------------------------------------
__global__ __launch_bounds__(256) void oproj_kernel(
    const float* __restrict__ Wo,  const float* __restrict__ bo,
    const float* __restrict__ Wao, const float* __restrict__ bao,
    float* __restrict__ out)
{
    __shared__ __align__(16) float As[16][68];
    __shared__ __align__(16) float Bs[16][68];

    const int tx = threadIdx.x, ty = threadIdx.y;
    const int t  = ty * 16 + tx;
    const int col0 = blockIdx.x * 64;
    const int row0 = blockIdx.y * 64;
    const bool is_enc = (row0 < S_TXT);
    const float* W    = is_enc ? Wao : Wo;
    const float* bias = is_enc ? bao : bo;

    const int lr = t >> 2, lq = t & 3;
    float acc[4][4];
    #pragma unroll
    for (int i = 0; i < 4; i++)
        #pragma unroll
        for (int j = 0; j < 4; j++) acc[i][j] = 0.f;

    const float* Ap = g_o + (size_t)(row0 + lr) * DM + lq * 4;
    const float* Bp = W   + (size_t)(col0 + lr) * DM + lq * 4;

    for (int k0 = 0; k0 < DM; k0 += 16) {
        float4 a4 = *(const float4*)(Ap + k0);
        float4 b4 = *(const float4*)(Bp + k0);
        As[lq*4+0][lr] = a4.x; As[lq*4+1][lr] = a4.y;
        As[lq*4+2][lr] = a4.z; As[lq*4+3][lr] = a4.w;
        Bs[lq*4+0][lr] = b4.x; Bs[lq*4+1][lr] = b4.y;
        Bs[lq*4+2][lr] = b4.z; Bs[lq*4+3][lr] = b4.w;
        __syncthreads();
        #pragma unroll
        for (int kk = 0; kk < 16; kk++) {
            float4 av  = *(const float4*)&As[kk][ty*4];
            float4 bv4 = *(const float4*)&Bs[kk][tx*4];
            const float ar[4] = {av.x, av.y, av.z, av.w};
            const float br[4] = {bv4.x, bv4.y, bv4.z, bv4.w};
            #pragma unroll
            for (int i = 0; i < 4; i++)
                #pragma unroll
                for (int j = 0; j < 4; j++)
                    acc[i][j] = fmaf(ar[i], br[j], acc[i][j]);
        }
        __syncthreads();
    }

    const int c0 = col0 + tx * 4;
    float bb[4];
    #pragma unroll
    for (int j = 0; j < 4; j++) bb[j] = bias[c0 + j];

    #pragma unroll
    for (int i = 0; i < 4; i++) {
        int s = row0 + ty * 4 + i;
        size_t orow = is_enc ? (size_t)(S_IMG + s) : (size_t)(s - S_TXT);
        float4 o;
        o.x = acc[i][0] + bb[0]; o.y = acc[i][1] + bb[1];
        o.z = acc[i][2] + bb[2]; o.w = acc[i][3] + bb[3];
        *(float4*)&out[orow * DM + c0] = o;
    }
}

// ---------------------------------------------------------------------------
extern "C" void kernel_launch(void* const* d_in, const int* in_sizes, int n_in,
                              void* d_out, int out_size)
{
    const float* hid = (const float*)d_in[0];
    const float* enc = (const float*)d_in[1];
    const float* rc  = (const float*)d_in[2];
    const float* rs  = (const float*)d_in[3];
    const float* Wq  = (const float*)d_in[4];
    const float* bq  = (const float*)d_in[5];
    const float* Wk  = (const float*)d_in[6];
    const float* bk  = (const float*)d_in[7];
    const float* Wv  = (const float*)d_in[8];
    const float* bv  = (const float*)d_in[9];
    const float* Waq = (const float*)d_in[10];
    const float* baq = (const float*)d_in[11];
    const float* Wak = (const float*)d_in[12];
    const float* bak = (const float*)d_in[13];
    const float* Wav = (const float*)d_in[14];
    const float* bav = (const float*)d_in[15];
    const float* Wo  = (const float*)d_in[16];
    const float* bo  = (const float*)d_in[17];
    const float* Wao = (const float*)d_in[18];
    const float* bao = (const float*)d_in[19];
    const float* gq  = (const float*)d_in[20];
    const float* gk  = (const float*)d_in[21];
    const float* gaq = (const float*)d_in[22];
    const float* gak = (const float*)d_in[23];
    float* out = (float*)d_out;

    dim3 blk(16, 16);
    qkv_kernel<<<dim3(72, 40), blk>>>(hid, enc, rc, rs,
                                      Wq, bq, Wk, bk, Wv, bv,
                                      Waq, baq, Wak, bak, Wav, bav,
                                      gq, gk, gaq, gak);

    size_t shm = (size_t)4 * 64 * 68 * sizeof(float);   // 69632 B
    cudaFuncSetAttribute(attn_kernel,
                         cudaFuncAttributeMaxDynamicSharedMemorySize, (int)shm);
    attn_kernel<<<dim3(40, 24), blk, shm>>>();

    oproj_kernel<<<dim3(24, 40), blk>>>(Wo, bo, Wao, bao, out);
}

// round 6
// speedup vs baseline: 1.4489x; 1.4489x over previous
#include <cuda_runtime.h>
#include <cuda_bf16.h>
#include <math.h>
#include <stdint.h>

#define S_TXT   512
#define S_IMG   2048
#define S_TOT   2560
#define DM      1536
#define NH      24
#define DH      64
#define SM_SCALE 0.125f

// Scratch (device globals: allocation-free rule)
__device__ __align__(16) float g_q[(size_t)NH * S_TOT * DH];
__device__ __align__(16) float g_k[(size_t)NH * S_TOT * DH];
__device__ __align__(16) float g_v[(size_t)NH * S_TOT * DH];
__device__ __align__(16) float g_o[(size_t)S_TOT * DM];

// ===========================================================================
// HMMA helpers (mma.sync + ldmatrix: baseline PTX, compiles for compute_103)
// ===========================================================================
__device__ __forceinline__ uint32_t smem_to_u32(const void* p) {
    uint32_t a;
    asm("{ .reg .u64 t; cvta.to.shared.u64 t, %1; cvt.u32.u64 %0, t; }"
        : "=r"(a) : "l"(p));
    return a;
}

__device__ __forceinline__ void ldsm_x4(uint32_t* r, uint32_t addr) {
    asm volatile("ldmatrix.sync.aligned.m8n8.x4.shared.b16 {%0,%1,%2,%3}, [%4];"
        : "=r"(r[0]), "=r"(r[1]), "=r"(r[2]), "=r"(r[3]) : "r"(addr));
}

__device__ __forceinline__ void mma16816(float* d, const uint32_t* a,
                                         const uint32_t* b) {
    asm volatile(
        "mma.sync.aligned.m16n8k16.row.col.f32.bf16.bf16.f32 "
        "{%0,%1,%2,%3}, {%4,%5,%6,%7}, {%8,%9}, {%0,%1,%2,%3};\n"
        : "+f"(d[0]), "+f"(d[1]), "+f"(d[2]), "+f"(d[3])
        : "r"(a[0]), "r"(a[1]), "r"(a[2]), "r"(a[3]), "r"(b[0]), "r"(b[1]));
}

// fp32 -> (bf16 hi, bf16 lo) split for 4 elements
__device__ __forceinline__ void cvt_split4(float4 v, uint2& hi, uint2& lo) {
    __nv_bfloat16 h0 = __float2bfloat16_rn(v.x);
    __nv_bfloat16 h1 = __float2bfloat16_rn(v.y);
    __nv_bfloat16 h2 = __float2bfloat16_rn(v.z);
    __nv_bfloat16 h3 = __float2bfloat16_rn(v.w);
    __nv_bfloat16 l0 = __float2bfloat16_rn(v.x - __bfloat162float(h0));
    __nv_bfloat16 l1 = __float2bfloat16_rn(v.y - __bfloat162float(h1));
    __nv_bfloat16 l2 = __float2bfloat16_rn(v.z - __bfloat162float(h2));
    __nv_bfloat16 l3 = __float2bfloat16_rn(v.w - __bfloat162float(h3));
    hi.x = (uint32_t)__bfloat16_as_ushort(h0) | ((uint32_t)__bfloat16_as_ushort(h1) << 16);
    hi.y = (uint32_t)__bfloat16_as_ushort(h2) | ((uint32_t)__bfloat16_as_ushort(h3) << 16);
    lo.x = (uint32_t)__bfloat16_as_ushort(l0) | ((uint32_t)__bfloat16_as_ushort(l1) << 16);
    lo.y = (uint32_t)__bfloat16_as_ushort(l2) | ((uint32_t)__bfloat16_as_ushort(l3) << 16);
}

// SMEM layout: bf16 tiles, 128 rows x 32 k, row pitch 40 bf16 = 80 B.
// 80B stride -> the 8 ldmatrix rows hit distinct 16B bank groups (conflict-free).
#define T_AHI 0
#define T_ALO 10240
#define T_BHI 20480
#define T_BLO 30720
#define C_PITCH 132
#define GEMM_SMEM_BYTES (128 * C_PITCH * 4)   // 67584; C tile aliases the k-loop tiles

// load a [128 rows x 32 k] fp32 tile, split to hi/lo bf16 into smem
__device__ __forceinline__ void load_split_32(
    const float* __restrict__ src, char* sm_hi, char* sm_lo, int t)
{
    #pragma unroll
    for (int i = 0; i < 4; i++) {
        int idx4 = i * 256 + t;            // 1024 float4s
        int row = idx4 >> 3, kq = idx4 & 7;
        float4 v = *(const float4*)(src + (size_t)row * DM + kq * 4);
        uint2 h, l;
        cvt_split4(v, h, l);
        *(uint2*)(sm_hi + row * 80 + kq * 8) = h;
        *(uint2*)(sm_lo + row * 80 + kq * 8) = l;
    }
}

// Core: C[128x128] = A[128 rows of DM] x B[128 rows of DM]^T  (bf16x3 split)
// Result left in smem as float[128][C_PITCH]. Caller must __syncthreads() after.
__device__ __forceinline__ void gemm_128x128(
    const float* __restrict__ Aptr, const float* __restrict__ Bptr,
    char* smem, uint32_t smem_base, int t)
{
    const int lane = t & 31;
    const int warp = t >> 5;
    const int wm = warp & 1;        // 2 m-blocks of 64
    const int wn = warp >> 1;       // 4 n-blocks of 32

    float acc[4][4][4];
    #pragma unroll
    for (int mt = 0; mt < 4; mt++)
        #pragma unroll
        for (int nt = 0; nt < 4; nt++)
            #pragma unroll
            for (int c = 0; c < 4; c++) acc[mt][nt][c] = 0.f;

    // ldmatrix lane-address components
    const int a_row = (lane & 7) + ((lane >> 3) & 1) * 8;   // bit3 -> row+8
    const int a_kof = ((lane >> 4) & 1) * 8;                // bit4 -> k+8
    const int b_row = (lane & 7) + ((lane >> 4) & 1) * 8;   // bit4 -> n+8
    const int b_kof = ((lane >> 3) & 1) * 8;                // bit3 -> k+8

    for (int kk = 0; kk < DM; kk += 32) {
        __syncthreads();
        load_split_32(Aptr + kk, smem + T_AHI, smem + T_ALO, t);
        load_split_32(Bptr + kk, smem + T_BHI, smem + T_BLO, t);
        __syncthreads();

        #pragma unroll
        for (int ks = 0; ks < 2; ks++) {
            uint32_t bh[4][2], bl[4][2];
            #pragma unroll
            for (int p = 0; p < 2; p++) {
                int n0 = wn * 32 + p * 16;
                uint32_t ba = smem_base +
                    (uint32_t)((n0 + b_row) * 80 + (ks * 16 + b_kof) * 2);
                uint32_t r[4];
                ldsm_x4(r, ba + T_BHI);
                bh[2*p][0] = r[0]; bh[2*p][1] = r[1];
                bh[2*p+1][0] = r[2]; bh[2*p+1][1] = r[3];
                ldsm_x4(r, ba + T_BLO);
                bl[2*p][0] = r[0]; bl[2*p][1] = r[1];
                bl[2*p+1][0] = r[2]; bl[2*p+1][1] = r[3];
            }
            #pragma unroll
            for (int mt = 0; mt < 4; mt++) {
                int m0 = wm * 64 + mt * 16;
                uint32_t aa = smem_base +
                    (uint32_t)((m0 + a_row) * 80 + (ks * 16 + a_kof) * 2);
                uint32_t ah[4], al[4];
                ldsm_x4(ah, aa + T_AHI);
                ldsm_x4(al, aa + T_ALO);
                #pragma unroll
                for (int nt = 0; nt < 4; nt++) {
                    mma16816(acc[mt][nt], ah, bh[nt]);
                    mma16816(acc[mt][nt], ah, bl[nt]);
                    mma16816(acc[mt][nt], al, bh[nt]);
                }
            }
        }
    }

    __syncthreads();   // everyone done reading tiles; C aliases them
    float* C = (float*)smem;
    #pragma unroll
    for (int mt = 0; mt < 4; mt++) {
        int row = wm * 64 + mt * 16 + (lane >> 2);
        #pragma unroll
        for (int nt = 0; nt < 4; nt++) {
            int col = wn * 32 + nt * 8 + (lane & 3) * 2;
            float2 v0 = {acc[mt][nt][0], acc[mt][nt][1]};
            float2 v1 = {acc[mt][nt][2], acc[mt][nt][3]};
            *(float2*)&C[(size_t)row * C_PITCH + col] = v0;
            *(float2*)&C[(size_t)(row + 8) * C_PITCH + col] = v1;
        }
    }
}

// ===========================================================================
// Kernel 1: QKV projection on HMMA (bf16x3), fused bias + RMSNorm + RoPE.
// grid.x: 36 (which = x/12, fcol0 = (x%12)*128), grid.y: 20 row tiles of 128.
// ===========================================================================
__global__ __launch_bounds__(256, 2) void qkv_mma_kernel(
    const float* __restrict__ hid, const float* __restrict__ enc,
    const float* __restrict__ rope_cos, const float* __restrict__ rope_sin,
    const float* __restrict__ Wq,  const float* __restrict__ bq,
    const float* __restrict__ Wk,  const float* __restrict__ bk,
    const float* __restrict__ Wv,  const float* __restrict__ bv,
    const float* __restrict__ Waq, const float* __restrict__ baq,
    const float* __restrict__ Wak, const float* __restrict__ bak,
    const float* __restrict__ Wav, const float* __restrict__ bav,
    const float* __restrict__ gq,  const float* __restrict__ gk,
    const float* __restrict__ gaq, const float* __restrict__ gak)
{
    extern __shared__ char smem[];
    const uint32_t smem_base = smem_to_u32(smem);
    const int t = threadIdx.x;

    const int cx = blockIdx.x;
    const int which = cx / 12;                 // 0=q,1=k,2=v
    const int fcol0 = (cx % 12) * 128;
    const int row0 = blockIdx.y * 128;
    const bool is_enc = (row0 < S_TXT);
    const float* X = is_enc ? enc : hid;
    const int xrow0 = is_enc ? row0 : (row0 - S_TXT);
    const float* W; const float* bias;
    if (which == 0)      { W = is_enc ? Waq : Wq; bias = is_enc ? baq : bq; }
    else if (which == 1) { W = is_enc ? Wak : Wk; bias = is_enc ? bak : bk; }
    else                 { W = is_enc ? Wav : Wv; bias = is_enc ? bav : bv; }

    gemm_128x128(X + (size_t)xrow0 * DM, W + (size_t)fcol0 * DM,
                 smem, smem_base, t);
    __syncthreads();

    // Epilogue: 256 threads, t&127 = row, t>>7 = head-in-tile. Full 64-dim
    // head per thread -> RMS needs no reduction.
    const float* C = (const float*)smem;
    const int row = t & 127;
    const int hj  = t >> 7;
    const int s = row0 + row;
    const int head = (fcol0 >> 6) + hj;
    const int cb = hj * 64;

    float x[64];
    #pragma unroll
    for (int c = 0; c < 64; c++)
        x[c] = C[(size_t)row * C_PITCH + cb + c] + bias[fcol0 + cb + c];

    if (which == 2) {
        float* dst = g_v + ((size_t)head * S_TOT + s) * DH;
        #pragma unroll
        for (int c = 0; c < 64; c += 4) {
            float4 o4 = {x[c], x[c+1], x[c+2], x[c+3]};
            *(float4*)(dst + c) = o4;
        }
    } else {
        const float* gvec = (which == 0) ? (is_enc ? gaq : gq)
                                         : (is_enc ? gak : gk);
        float ssq = 0.f;
        #pragma unroll
        for (int c = 0; c < 64; c++) ssq = fmaf(x[c], x[c], ssq);
        float rn = rsqrtf(ssq * (1.0f / DH) + 1e-6f);
        const float* cp = rope_cos + (size_t)s * DH;
        const float* sp = rope_sin + (size_t)s * DH;
        float* dst = ((which == 0) ? g_q : g_k) + ((size_t)head * S_TOT + s) * DH;
        #pragma unroll
        for (int c = 0; c < 64; c += 4) {
            float x0 = x[c]   * rn * gvec[c];
            float x1 = x[c+1] * rn * gvec[c+1];
            float x2 = x[c+2] * rn * gvec[c+2];
            float x3 = x[c+3] * rn * gvec[c+3];
            float4 o4;
            o4.x = x0 * cp[c]   - x1 * sp[c];
            o4.y = x1 * cp[c+1] + x0 * sp[c+1];
            o4.z = x2 * cp[c+2] - x3 * sp[c+2];
            o4.w = x3 * cp[c+3] + x2 * sp[c+3];
            *(float4*)(dst + c) = o4;
        }
    }
}

// ===========================================================================
// Kernel 3: output projection on HMMA (bf16x3), bias + row reorder.
// ===========================================================================
__global__ __launch_bounds__(256, 2) void oproj_mma_kernel(
    const float* __restrict__ Wo,  const float* __restrict__ bo,
    const float* __restrict__ Wao, const float* __restrict__ bao,
    float* __restrict__ out)
{
    extern __shared__ char smem[];
    const uint32_t smem_base = smem_to_u32(smem);
    const int t = threadIdx.x;

    const int col0 = blockIdx.x * 128;
    const int row0 = blockIdx.y * 128;
    const bool is_enc = (row0 < S_TXT);
    const float* W    = is_enc ? Wao : Wo;
    const float* bias = is_enc ? bao : bo;

    gemm_128x128(g_o + (size_t)row0 * DM, W + (size_t)col0 * DM,
                 smem, smem_base, t);
    __syncthreads();

    const float* C = (const float*)smem;
    const int row = t >> 1;
    const int half = t & 1;
    const int s = row0 + row;
    const size_t orow = is_enc ? (size_t)(S_IMG + s) : (size_t)(s - S_TXT);
    float* dst = out + orow * DM + col0 + half * 64;
    const float* bsrc = bias + col0 + half * 64;
    const float* csrc = C + (size_t)row * C_PITCH + half * 64;
    #pragma unroll
    for (int c = 0; c < 64; c += 4) {
        float4 o4;
        o4.x = csrc[c]   + bsrc[c];
        o4.y = csrc[c+1] + bsrc[c+1];
        o4.z = csrc[c+2] + bsrc[c+2];
        o4.w = csrc[c+3] + bsrc[c+3];
        *(float4*)(dst + c) = o4;
    }
}

// ---------------------------------------------------------------------------
// Kernel 2: flash attention (unchanged from passing round).
// ---------------------------------------------------------------------------
__global__ __launch_bounds__(256) void attn_kernel()
{
    extern __shared__ __align__(16) float sm[];
    float* Qs = sm;              // [d][row]  64x68
    float* Ks = Qs + 64 * 68;    // [d][col]  64x68
    float* Vs = Ks + 64 * 68;    // [kr][d]   64x68
    float* Ps = Vs + 64 * 68;    // [row][col]64x68

    const int h  = blockIdx.y;
    const int q0 = blockIdx.x * 64;
    const int tx = threadIdx.x, ty = threadIdx.y;
    const int t  = ty * 16 + tx;

    const float* Qg = g_q + (size_t)h * S_TOT * DH;
    const float* Kg = g_k + (size_t)h * S_TOT * DH;
    const float* Vg = g_v + (size_t)h * S_TOT * DH;

    #pragma unroll
    for (int ii = 0; ii < 4; ii++) {
        int idx = ii * 256 + t;
        int r = idx >> 4, qd = idx & 15;
        float4 v = *(const float4*)(Qg + (size_t)(q0 + r) * DH + qd * 4);
        Qs[(qd*4+0)*68 + r] = v.x;
        Qs[(qd*4+1)*68 + r] = v.y;
        Qs[(qd*4+2)*68 + r] = v.z;
        Qs[(qd*4+3)*68 + r] = v.w;
    }

    float m_[4], l_[4], o_[4][4];
    #pragma unroll
    for (int i = 0; i < 4; i++) {
        m_[i] = -1e30f; l_[i] = 0.f;
        #pragma unroll
        for (int j = 0; j < 4; j++) o_[i][j] = 0.f;
    }

    for (int k0 = 0; k0 < S_TOT; k0 += 64) {
        __syncthreads();
        #pragma unroll
        for (int ii = 0; ii < 4; ii++) {
            int idx = ii * 256 + t;
            int r = idx >> 4, qd = idx & 15;
            float4 kv = *(const float4*)(Kg + (size_t)(k0 + r) * DH + qd * 4);
            Ks[(qd*4+0)*68 + r] = kv.x;
            Ks[(qd*4+1)*68 + r] = kv.y;
            Ks[(qd*4+2)*68 + r] = kv.z;
            Ks[(qd*4+3)*68 + r] = kv.w;
            float4 vv = *(const float4*)(Vg + (size_t)(k0 + r) * DH + qd * 4);
            *(float4*)&Vs[r*68 + qd*4] = vv;
        }
        __syncthreads();

        float sa[4][4];
        #pragma unroll
        for (int i = 0; i < 4; i++)
            #pragma unroll
            for (int j = 0; j < 4; j++) sa[i][j] = 0.f;

        #pragma unroll 8
        for (int d = 0; d < 64; d++) {
            float4 a = *(const float4*)&Qs[d*68 + ty*4];
            float4 b = *(const float4*)&Ks[d*68 + tx*4];
            const float ar[4] = {a.x, a.y, a.z, a.w};
            const float br[4] = {b.x, b.y, b.z, b.w};
            #pragma unroll
            for (int i = 0; i < 4; i++)
                #pragma unroll
                for (int j = 0; j < 4; j++)
                    sa[i][j] = fmaf(ar[i], br[j], sa[i][j]);
        }

        #pragma unroll
        for (int i = 0; i < 4; i++) {
            float s0 = sa[i][0]*SM_SCALE, s1 = sa[i][1]*SM_SCALE;
            float s2 = sa[i][2]*SM_SCALE, s3 = sa[i][3]*SM_SCALE;
            float mx = fmaxf(fmaxf(s0, s1), fmaxf(s2, s3));
            #pragma unroll
            for (int m = 1; m < 16; m <<= 1)
                mx = fmaxf(mx, __shfl_xor_sync(0xffffffffu, mx, m));
            float mn = fmaxf(m_[i], mx);
            float alpha = __expf(m_[i] - mn);
            float p0 = __expf(s0 - mn), p1 = __expf(s1 - mn);
            float p2 = __expf(s2 - mn), p3 = __expf(s3 - mn);
            float rs = (p0 + p1) + (p2 + p3);
            #pragma unroll
            for (int m = 1; m < 16; m <<= 1)
                rs += __shfl_xor_sync(0xffffffffu, rs, m);
            l_[i] = l_[i] * alpha + rs;
            m_[i] = mn;
            #pragma unroll
            for (int j = 0; j < 4; j++) o_[i][j] *= alpha;
            float4 pp; pp.x = p0; pp.y = p1; pp.z = p2; pp.w = p3;
            *(float4*)&Ps[(ty*4+i)*68 + tx*4] = pp;
        }
        __syncthreads();

        #pragma unroll 4
        for (int jj = 0; jj < 64; jj += 4) {
            float pr[4][4];
            #pragma unroll
            for (int i = 0; i < 4; i++) {
                float4 pv = *(const float4*)&Ps[(ty*4+i)*68 + jj];
                pr[i][0] = pv.x; pr[i][1] = pv.y; pr[i][2] = pv.z; pr[i][3] = pv.w;
            }
            #pragma unroll
            for (int u = 0; u < 4; u++) {
                float4 vv = *(const float4*)&Vs[(jj+u)*68 + tx*4];
                const float vr[4] = {vv.x, vv.y, vv.z, vv.w};
                #pragma unroll
                for (int i = 0; i < 4; i++)
                    #pragma unroll
                    for (int j = 0; j < 4; j++)
                        o_[i][j] = fmaf(pr[i][u], vr[j], o_[i][j]);
            }
        }
    }

    #pragma unroll
    for (int i = 0; i < 4; i++) {
        float inv = 1.0f / l_[i];
        int s = q0 + ty * 4 + i;
        float4 o;
        o.x = o_[i][0]*inv; o.y = o_[i][1]*inv;
        o.z = o_[i][2]*inv; o.w = o_[i][3]*inv;
        *(float4*)&g_o[(size_t)s * DM + h * DH + tx * 4] = o;
    }
}

// ---------------------------------------------------------------------------
extern "C" void kernel_launch(void* const* d_in, const int* in_sizes, int n_in,
                              void* d_out, int out_size)
{
    const float* hid = (const float*)d_in[0];
    const float* enc = (const float*)d_in[1];
    const float* rc  = (const float*)d_in[2];
    const float* rs  = (const float*)d_in[3];
    const float* Wq  = (const float*)d_in[4];
    const float* bq  = (const float*)d_in[5];
    const float* Wk  = (const float*)d_in[6];
    const float* bk  = (const float*)d_in[7];
    const float* Wv  = (const float*)d_in[8];
    const float* bv  = (const float*)d_in[9];
    const float* Waq = (const float*)d_in[10];
    const float* baq = (const float*)d_in[11];
    const float* Wak = (const float*)d_in[12];
    const float* bak = (const float*)d_in[13];
    const float* Wav = (const float*)d_in[14];
    const float* bav = (const float*)d_in[15];
    const float* Wo  = (const float*)d_in[16];
    const float* bo  = (const float*)d_in[17];
    const float* Wao = (const float*)d_in[18];
    const float* bao = (const float*)d_in[19];
    const float* gq  = (const float*)d_in[20];
    const float* gk  = (const float*)d_in[21];
    const float* gaq = (const float*)d_in[22];
    const float* gak = (const float*)d_in[23];
    float* out = (float*)d_out;

    cudaFuncSetAttribute(qkv_mma_kernel,
                         cudaFuncAttributeMaxDynamicSharedMemorySize, GEMM_SMEM_BYTES);
    cudaFuncSetAttribute(oproj_mma_kernel,
                         cudaFuncAttributeMaxDynamicSharedMemorySize, GEMM_SMEM_BYTES);
    cudaFuncSetAttribute(attn_kernel,
                         cudaFuncAttributeMaxDynamicSharedMemorySize, 4 * 64 * 68 * 4);

    qkv_mma_kernel<<<dim3(36, 20), 256, GEMM_SMEM_BYTES>>>(
        hid, enc, rc, rs, Wq, bq, Wk, bk, Wv, bv,
        Waq, baq, Wak, bak, Wav, bav, gq, gk, gaq, gak);

    attn_kernel<<<dim3(40, 24), dim3(16, 16), 4 * 64 * 68 * 4>>>();

    oproj_mma_kernel<<<dim3(12, 20), 256, GEMM_SMEM_BYTES>>>(Wo, bo, Wao, bao, out);
}

// round 7
// speedup vs baseline: 2.5186x; 1.7383x over previous
#include <cuda_runtime.h>
#include <cuda_bf16.h>
#include <math.h>
#include <stdint.h>

#define S_TXT   512
#define S_IMG   2048
#define S_TOT   2560
#define DM      1536
#define NH      24
#define DH      64
#define SM_SCALE 0.125f

// Scratch (device globals: allocation-free rule)
__device__ __align__(16) float g_q[(size_t)NH * S_TOT * DH];
__device__ __align__(16) float g_k[(size_t)NH * S_TOT * DH];
__device__ __align__(16) float g_v[(size_t)NH * S_TOT * DH];
__device__ __align__(16) float g_o[(size_t)S_TOT * DM];

// ===========================================================================
// HMMA helpers (mma.sync + ldmatrix: baseline PTX, compiles for compute_103)
// ===========================================================================
__device__ __forceinline__ uint32_t smem_to_u32(const void* p) {
    uint32_t a;
    asm("{ .reg .u64 t; cvta.to.shared.u64 t, %1; cvt.u32.u64 %0, t; }"
        : "=r"(a) : "l"(p));
    return a;
}

__device__ __forceinline__ void ldsm_x4(uint32_t* r, uint32_t addr) {
    asm volatile("ldmatrix.sync.aligned.m8n8.x4.shared.b16 {%0,%1,%2,%3}, [%4];"
        : "=r"(r[0]), "=r"(r[1]), "=r"(r[2]), "=r"(r[3]) : "r"(addr));
}
__device__ __forceinline__ void ldsm_x4_t(uint32_t* r, uint32_t addr) {
    asm volatile("ldmatrix.sync.aligned.m8n8.x4.trans.shared.b16 {%0,%1,%2,%3}, [%4];"
        : "=r"(r[0]), "=r"(r[1]), "=r"(r[2]), "=r"(r[3]) : "r"(addr));
}

__device__ __forceinline__ void mma16816(float* d, const uint32_t* a,
                                         const uint32_t* b) {
    asm volatile(
        "mma.sync.aligned.m16n8k16.row.col.f32.bf16.bf16.f32 "
        "{%0,%1,%2,%3}, {%4,%5,%6,%7}, {%8,%9}, {%0,%1,%2,%3};\n"
        : "+f"(d[0]), "+f"(d[1]), "+f"(d[2]), "+f"(d[3])
        : "r"(a[0]), "r"(a[1]), "r"(a[2]), "r"(a[3]), "r"(b[0]), "r"(b[1]));
}

// pack two f32 -> bf16x2 (lo in low half, hi in high half)
__device__ __forceinline__ uint32_t pack_bf16x2(float lo, float hi) {
    uint32_t r;
    asm("cvt.rn.bf16x2.f32 %0, %1, %2;" : "=r"(r) : "f"(hi), "f"(lo));
    return r;
}

// fp32 -> (bf16 hi, bf16 lo) split for 4 elements
__device__ __forceinline__ void cvt_split4(float4 v, uint2& hi, uint2& lo) {
    __nv_bfloat16 h0 = __float2bfloat16_rn(v.x);
    __nv_bfloat16 h1 = __float2bfloat16_rn(v.y);
    __nv_bfloat16 h2 = __float2bfloat16_rn(v.z);
    __nv_bfloat16 h3 = __float2bfloat16_rn(v.w);
    __nv_bfloat16 l0 = __float2bfloat16_rn(v.x - __bfloat162float(h0));
    __nv_bfloat16 l1 = __float2bfloat16_rn(v.y - __bfloat162float(h1));
    __nv_bfloat16 l2 = __float2bfloat16_rn(v.z - __bfloat162float(h2));
    __nv_bfloat16 l3 = __float2bfloat16_rn(v.w - __bfloat162float(h3));
    hi.x = (uint32_t)__bfloat16_as_ushort(h0) | ((uint32_t)__bfloat16_as_ushort(h1) << 16);
    hi.y = (uint32_t)__bfloat16_as_ushort(h2) | ((uint32_t)__bfloat16_as_ushort(h3) << 16);
    lo.x = (uint32_t)__bfloat16_as_ushort(l0) | ((uint32_t)__bfloat16_as_ushort(l1) << 16);
    lo.y = (uint32_t)__bfloat16_as_ushort(l2) | ((uint32_t)__bfloat16_as_ushort(l3) << 16);
}

// ===========================================================================
// Projection GEMM machinery (unchanged from passing round 6)
// ===========================================================================
#define T_AHI 0
#define T_ALO 10240
#define T_BHI 20480
#define T_BLO 30720
#define C_PITCH 132
#define GEMM_SMEM_BYTES (128 * C_PITCH * 4)

__device__ __forceinline__ void load_split_32(
    const float* __restrict__ src, char* sm_hi, char* sm_lo, int t)
{
    #pragma unroll
    for (int i = 0; i < 4; i++) {
        int idx4 = i * 256 + t;
        int row = idx4 >> 3, kq = idx4 & 7;
        float4 v = *(const float4*)(src + (size_t)row * DM + kq * 4);
        uint2 h, l;
        cvt_split4(v, h, l);
        *(uint2*)(sm_hi + row * 80 + kq * 8) = h;
        *(uint2*)(sm_lo + row * 80 + kq * 8) = l;
    }
}

__device__ __forceinline__ void gemm_128x128(
    const float* __restrict__ Aptr, const float* __restrict__ Bptr,
    char* smem, uint32_t smem_base, int t)
{
    const int lane = t & 31;
    const int warp = t >> 5;
    const int wm = warp & 1;
    const int wn = warp >> 1;

    float acc[4][4][4];
    #pragma unroll
    for (int mt = 0; mt < 4; mt++)
        #pragma unroll
        for (int nt = 0; nt < 4; nt++)
            #pragma unroll
            for (int c = 0; c < 4; c++) acc[mt][nt][c] = 0.f;

    const int a_row = (lane & 7) + ((lane >> 3) & 1) * 8;
    const int a_kof = ((lane >> 4) & 1) * 8;
    const int b_row = (lane & 7) + ((lane >> 4) & 1) * 8;
    const int b_kof = ((lane >> 3) & 1) * 8;

    for (int kk = 0; kk < DM; kk += 32) {
        __syncthreads();
        load_split_32(Aptr + kk, smem + T_AHI, smem + T_ALO, t);
        load_split_32(Bptr + kk, smem + T_BHI, smem + T_BLO, t);
        __syncthreads();

        #pragma unroll
        for (int ks = 0; ks < 2; ks++) {
            uint32_t bh[4][2], bl[4][2];
            #pragma unroll
            for (int p = 0; p < 2; p++) {
                int n0 = wn * 32 + p * 16;
                uint32_t ba = smem_base +
                    (uint32_t)((n0 + b_row) * 80 + (ks * 16 + b_kof) * 2);
                uint32_t r[4];
                ldsm_x4(r, ba + T_BHI);
                bh[2*p][0] = r[0]; bh[2*p][1] = r[1];
                bh[2*p+1][0] = r[2]; bh[2*p+1][1] = r[3];
                ldsm_x4(r, ba + T_BLO);
                bl[2*p][0] = r[0]; bl[2*p][1] = r[1];
                bl[2*p+1][0] = r[2]; bl[2*p+1][1] = r[3];
            }
            #pragma unroll
            for (int mt = 0; mt < 4; mt++) {
                int m0 = wm * 64 + mt * 16;
                uint32_t aa = smem_base +
                    (uint32_t)((m0 + a_row) * 80 + (ks * 16 + a_kof) * 2);
                uint32_t ah[4], al[4];
                ldsm_x4(ah, aa + T_AHI);
                ldsm_x4(al, aa + T_ALO);
                #pragma unroll
                for (int nt = 0; nt < 4; nt++) {
                    mma16816(acc[mt][nt], ah, bh[nt]);
                    mma16816(acc[mt][nt], ah, bl[nt]);
                    mma16816(acc[mt][nt], al, bh[nt]);
                }
            }
        }
    }

    __syncthreads();
    float* C = (float*)smem;
    #pragma unroll
    for (int mt = 0; mt < 4; mt++) {
        int row = wm * 64 + mt * 16 + (lane >> 2);
        #pragma unroll
        for (int nt = 0; nt < 4; nt++) {
            int col = wn * 32 + nt * 8 + (lane & 3) * 2;
            float2 v0 = {acc[mt][nt][0], acc[mt][nt][1]};
            float2 v1 = {acc[mt][nt][2], acc[mt][nt][3]};
            *(float2*)&C[(size_t)row * C_PITCH + col] = v0;
            *(float2*)&C[(size_t)(row + 8) * C_PITCH + col] = v1;
        }
    }
}

// ===========================================================================
// Kernel 1: QKV projection (HMMA bf16x3) + bias + RMSNorm + RoPE (unchanged)
// ===========================================================================
__global__ __launch_bounds__(256, 2) void qkv_mma_kernel(
    const float* __restrict__ hid, const float* __restrict__ enc,
    const float* __restrict__ rope_cos, const float* __restrict__ rope_sin,
    const float* __restrict__ Wq,  const float* __restrict__ bq,
    const float* __restrict__ Wk,  const float* __restrict__ bk,
    const float* __restrict__ Wv,  const float* __restrict__ bv,
    const float* __restrict__ Waq, const float* __restrict__ baq,
    const float* __restrict__ Wak, const float* __restrict__ bak,
    const float* __restrict__ Wav, const float* __restrict__ bav,
    const float* __restrict__ gq,  const float* __restrict__ gk,
    const float* __restrict__ gaq, const float* __restrict__ gak)
{
    extern __shared__ char smem[];
    const uint32_t smem_base = smem_to_u32(smem);
    const int t = threadIdx.x;

    const int cx = blockIdx.x;
    const int which = cx / 12;
    const int fcol0 = (cx % 12) * 128;
    const int row0 = blockIdx.y * 128;
    const bool is_enc = (row0 < S_TXT);
    const float* X = is_enc ? enc : hid;
    const int xrow0 = is_enc ? row0 : (row0 - S_TXT);
    const float* W; const float* bias;
    if (which == 0)      { W = is_enc ? Waq : Wq; bias = is_enc ? baq : bq; }
    else if (which == 1) { W = is_enc ? Wak : Wk; bias = is_enc ? bak : bk; }
    else                 { W = is_enc ? Wav : Wv; bias = is_enc ? bav : bv; }

    gemm_128x128(X + (size_t)xrow0 * DM, W + (size_t)fcol0 * DM,
                 smem, smem_base, t);
    __syncthreads();

    const float* C = (const float*)smem;
    const int row = t & 127;
    const int hj  = t >> 7;
    const int s = row0 + row;
    const int head = (fcol0 >> 6) + hj;
    const int cb = hj * 64;

    float x[64];
    #pragma unroll
    for (int c = 0; c < 64; c++)
        x[c] = C[(size_t)row * C_PITCH + cb + c] + bias[fcol0 + cb + c];

    if (which == 2) {
        float* dst = g_v + ((size_t)head * S_TOT + s) * DH;
        #pragma unroll
        for (int c = 0; c < 64; c += 4) {
            float4 o4 = {x[c], x[c+1], x[c+2], x[c+3]};
            *(float4*)(dst + c) = o4;
        }
    } else {
        const float* gvec = (which == 0) ? (is_enc ? gaq : gq)
                                         : (is_enc ? gak : gk);
        float ssq = 0.f;
        #pragma unroll
        for (int c = 0; c < 64; c++) ssq = fmaf(x[c], x[c], ssq);
        float rn = rsqrtf(ssq * (1.0f / DH) + 1e-6f);
        const float* cp = rope_cos + (size_t)s * DH;
        const float* sp = rope_sin + (size_t)s * DH;
        float* dst = ((which == 0) ? g_q : g_k) + ((size_t)head * S_TOT + s) * DH;
        #pragma unroll
        for (int c = 0; c < 64; c += 4) {
            float x0 = x[c]   * rn * gvec[c];
            float x1 = x[c+1] * rn * gvec[c+1];
            float x2 = x[c+2] * rn * gvec[c+2];
            float x3 = x[c+3] * rn * gvec[c+3];
            float4 o4;
            o4.x = x0 * cp[c]   - x1 * sp[c];
            o4.y = x1 * cp[c+1] + x0 * sp[c+1];
            o4.z = x2 * cp[c+2] - x3 * sp[c+2];
            o4.w = x3 * cp[c+3] + x2 * sp[c+3];
            *(float4*)(dst + c) = o4;
        }
    }
}

// ===========================================================================
// Kernel 3: output projection (HMMA bf16x3) + bias + row reorder (unchanged)
// ===========================================================================
__global__ __launch_bounds__(256, 2) void oproj_mma_kernel(
    const float* __restrict__ Wo,  const float* __restrict__ bo,
    const float* __restrict__ Wao, const float* __restrict__ bao,
    float* __restrict__ out)
{
    extern __shared__ char smem[];
    const uint32_t smem_base = smem_to_u32(smem);
    const int t = threadIdx.x;

    const int col0 = blockIdx.x * 128;
    const int row0 = blockIdx.y * 128;
    const bool is_enc = (row0 < S_TXT);
    const float* W    = is_enc ? Wao : Wo;
    const float* bias = is_enc ? bao : bo;

    gemm_128x128(g_o + (size_t)row0 * DM, W + (size_t)col0 * DM,
                 smem, smem_base, t);
    __syncthreads();

    const float* C = (const float*)smem;
    const int row = t >> 1;
    const int half = t & 1;
    const int s = row0 + row;
    const size_t orow = is_enc ? (size_t)(S_IMG + s) : (size_t)(s - S_TXT);
    float* dst = out + orow * DM + col0 + half * 64;
    const float* bsrc = bias + col0 + half * 64;
    const float* csrc = C + (size_t)row * C_PITCH + half * 64;
    #pragma unroll
    for (int c = 0; c < 64; c += 4) {
        float4 o4;
        o4.x = csrc[c]   + bsrc[c];
        o4.y = csrc[c+1] + bsrc[c+1];
        o4.z = csrc[c+2] + bsrc[c+2];
        o4.w = csrc[c+3] + bsrc[c+3];
        *(float4*)(dst + c) = o4;
    }
}

// ===========================================================================
// Kernel 2: flash attention on HMMA (bf16x3 for QK^T and PV).
// grid = (20 q-tiles of 128, 24 heads), 256 threads (8 warps x 16 q-rows).
// SMEM: V hi/lo at [0, 36864) (aliases Q staging), K hi/lo at [36864, 73728).
// Tiles [128 rows][64 cols bf16], pitch 144B (conflict-free ldmatrix).
// ===========================================================================
#define AP 144
#define VOFF_HI 0
#define VOFF_LO 18432
#define KOFF_HI 36864
#define KOFF_LO 55296
#define ATTN_SMEM 73728

__global__ __launch_bounds__(256) void attn_mma_kernel()
{
    extern __shared__ char smem[];
    const uint32_t smem_base = smem_to_u32(smem);
    const int t = threadIdx.x;
    const int lane = t & 31, warp = t >> 5;
    const int h = blockIdx.y;
    const int q0 = blockIdx.x * 128;

    const float* Qg = g_q + ((size_t)h * S_TOT + q0) * DH;
    const float* Kg = g_k + (size_t)h * S_TOT * DH;
    const float* Vg = g_v + (size_t)h * S_TOT * DH;

    // ---- load Q tile (scaled), split, stage in smem (V region) ----
    #pragma unroll
    for (int i = 0; i < 8; i++) {
        int idx4 = i * 256 + t;
        int row = idx4 >> 4, dq = idx4 & 15;
        float4 v = *(const float4*)(Qg + row * 64 + dq * 4);
        v.x *= SM_SCALE; v.y *= SM_SCALE; v.z *= SM_SCALE; v.w *= SM_SCALE;
        uint2 hh, ll;
        cvt_split4(v, hh, ll);
        *(uint2*)(smem + VOFF_HI + row * AP + dq * 8) = hh;
        *(uint2*)(smem + VOFF_LO + row * AP + dq * 8) = ll;
    }
    __syncthreads();

    // ---- build persistent Q fragments (16 rows per warp, k = 64) ----
    const int a_row = (lane & 7) + ((lane >> 3) & 1) * 8;
    const int a_kof = ((lane >> 4) & 1) * 8;
    uint32_t qh[4][4], ql[4][4];
    #pragma unroll
    for (int ks = 0; ks < 4; ks++) {
        uint32_t aa = smem_base +
            (uint32_t)((warp * 16 + a_row) * AP + (ks * 16 + a_kof) * 2);
        ldsm_x4(qh[ks], aa + VOFF_HI);
        ldsm_x4(ql[ks], aa + VOFF_LO);
    }

    const int b_row = (lane & 7) + ((lane >> 4) & 1) * 8;
    const int b_kof = ((lane >> 3) & 1) * 8;
    const int v_row = (lane & 7) + ((lane >> 3) & 1) * 8;   // trans: key index
    const int v_col = ((lane >> 4) & 1) * 8;                // trans: dh offset

    float m0 = -1e30f, m1 = -1e30f, l0 = 0.f, l1 = 0.f;
    float oacc[8][4];
    #pragma unroll
    for (int nv = 0; nv < 8; nv++)
        #pragma unroll
        for (int c = 0; c < 4; c++) oacc[nv][c] = 0.f;

    for (int kt = 0; kt < S_TOT / 128; kt++) {
        const int k0 = kt * 128;
        __syncthreads();   // everyone done with K/V (and Q staging on iter 0)
        const float* Kt = Kg + (size_t)k0 * DH;
        const float* Vt = Vg + (size_t)k0 * DH;
        #pragma unroll
        for (int i = 0; i < 8; i++) {
            int idx4 = i * 256 + t;
            int row = idx4 >> 4, dq = idx4 & 15;
            float4 kv = *(const float4*)(Kt + row * 64 + dq * 4);
            uint2 hh, ll;
            cvt_split4(kv, hh, ll);
            *(uint2*)(smem + KOFF_HI + row * AP + dq * 8) = hh;
            *(uint2*)(smem + KOFF_LO + row * AP + dq * 8) = ll;
            float4 vv = *(const float4*)(Vt + row * 64 + dq * 4);
            cvt_split4(vv, hh, ll);
            *(uint2*)(smem + VOFF_HI + row * AP + dq * 8) = hh;
            *(uint2*)(smem + VOFF_LO + row * AP + dq * 8) = ll;
        }
        __syncthreads();

        // ---- S = Q K^T : 16 rows x 128 keys per warp ----
        float sacc[16][4];
        #pragma unroll
        for (int nt = 0; nt < 16; nt++)
            #pragma unroll
            for (int c = 0; c < 4; c++) sacc[nt][c] = 0.f;

        #pragma unroll
        for (int ks = 0; ks < 4; ks++) {
            #pragma unroll
            for (int ntp = 0; ntp < 8; ntp++) {
                uint32_t ba = smem_base +
                    (uint32_t)((ntp * 16 + b_row) * AP + (ks * 16 + b_kof) * 2);
                uint32_t kh[4], kl[4];
                ldsm_x4(kh, ba + KOFF_HI);
                ldsm_x4(kl, ba + KOFF_LO);
                mma16816(sacc[2*ntp],   qh[ks], kh + 0);
                mma16816(sacc[2*ntp],   qh[ks], kl + 0);
                mma16816(sacc[2*ntp],   ql[ks], kh + 0);
                mma16816(sacc[2*ntp+1], qh[ks], kh + 2);
                mma16816(sacc[2*ntp+1], qh[ks], kl + 2);
                mma16816(sacc[2*ntp+1], ql[ks], kh + 2);
            }
        }

        // ---- online softmax (rows r0 = warp*16+lane/4, r1 = r0+8) ----
        float mx0 = -1e30f, mx1 = -1e30f;
        #pragma unroll
        for (int nt = 0; nt < 16; nt++) {
            mx0 = fmaxf(mx0, fmaxf(sacc[nt][0], sacc[nt][1]));
            mx1 = fmaxf(mx1, fmaxf(sacc[nt][2], sacc[nt][3]));
        }
        mx0 = fmaxf(mx0, __shfl_xor_sync(0xffffffffu, mx0, 1));
        mx0 = fmaxf(mx0, __shfl_xor_sync(0xffffffffu, mx0, 2));
        mx1 = fmaxf(mx1, __shfl_xor_sync(0xffffffffu, mx1, 1));
        mx1 = fmaxf(mx1, __shfl_xor_sync(0xffffffffu, mx1, 2));
        float mn0 = fmaxf(m0, mx0), mn1 = fmaxf(m1, mx1);
        float al0 = __expf(m0 - mn0), al1 = __expf(m1 - mn1);
        m0 = mn0; m1 = mn1;

        float rs0 = 0.f, rs1 = 0.f;
        #pragma unroll
        for (int nt = 0; nt < 16; nt++) {
            float p0 = __expf(sacc[nt][0] - m0);
            float p1 = __expf(sacc[nt][1] - m0);
            float p2 = __expf(sacc[nt][2] - m1);
            float p3 = __expf(sacc[nt][3] - m1);
            rs0 += p0 + p1; rs1 += p2 + p3;
            uint32_t h01 = pack_bf16x2(p0, p1);
            uint32_t h23 = pack_bf16x2(p2, p3);
            float r0f = p0 - __uint_as_float(h01 << 16);
            float r1f = p1 - __uint_as_float(h01 & 0xffff0000u);
            float r2f = p2 - __uint_as_float(h23 << 16);
            float r3f = p3 - __uint_as_float(h23 & 0xffff0000u);
            sacc[nt][0] = __uint_as_float(h01);
            sacc[nt][1] = __uint_as_float(pack_bf16x2(r0f, r1f));
            sacc[nt][2] = __uint_as_float(h23);
            sacc[nt][3] = __uint_as_float(pack_bf16x2(r2f, r3f));
        }
        rs0 += __shfl_xor_sync(0xffffffffu, rs0, 1);
        rs0 += __shfl_xor_sync(0xffffffffu, rs0, 2);
        rs1 += __shfl_xor_sync(0xffffffffu, rs1, 1);
        rs1 += __shfl_xor_sync(0xffffffffu, rs1, 2);
        l0 = l0 * al0 + rs0;
        l1 = l1 * al1 + rs1;
        #pragma unroll
        for (int nv = 0; nv < 8; nv++) {
            oacc[nv][0] *= al0; oacc[nv][1] *= al0;
            oacc[nv][2] *= al1; oacc[nv][3] *= al1;
        }

        // ---- O += P V : A-frags come straight from sacc registers ----
        #pragma unroll
        for (int kp = 0; kp < 8; kp++) {
            uint32_t pa[4], pl[4];
            pa[0] = __float_as_uint(sacc[2*kp][0]);
            pa[1] = __float_as_uint(sacc[2*kp][2]);
            pa[2] = __float_as_uint(sacc[2*kp+1][0]);
            pa[3] = __float_as_uint(sacc[2*kp+1][2]);
            pl[0] = __float_as_uint(sacc[2*kp][1]);
            pl[1] = __float_as_uint(sacc[2*kp][3]);
            pl[2] = __float_as_uint(sacc[2*kp+1][1]);
            pl[3] = __float_as_uint(sacc[2*kp+1][3]);
            #pragma unroll
            for (int nv2 = 0; nv2 < 4; nv2++) {
                uint32_t va = smem_base +
                    (uint32_t)((kp * 16 + v_row) * AP + (nv2 * 16 + v_col) * 2);
                uint32_t vh[4], vl[4];
                ldsm_x4_t(vh, va + VOFF_HI);
                ldsm_x4_t(vl, va + VOFF_LO);
                mma16816(oacc[2*nv2],   pa, vh + 0);
                mma16816(oacc[2*nv2],   pa, vl + 0);
                mma16816(oacc[2*nv2],   pl, vh + 0);
                mma16816(oacc[2*nv2+1], pa, vh + 2);
                mma16816(oacc[2*nv2+1], pa, vl + 2);
                mma16816(oacc[2*nv2+1], pl, vh + 2);
            }
        }
    }

    // ---- epilogue ----
    float inv0 = 1.0f / l0, inv1 = 1.0f / l1;
    const int r0 = q0 + warp * 16 + (lane >> 2);
    #pragma unroll
    for (int nv = 0; nv < 8; nv++) {
        int col = h * 64 + nv * 8 + 2 * (lane & 3);
        float2 w0 = {oacc[nv][0] * inv0, oacc[nv][1] * inv0};
        float2 w1 = {oacc[nv][2] * inv1, oacc[nv][3] * inv1};
        *(float2*)&g_o[(size_t)r0 * DM + col] = w0;
        *(float2*)&g_o[(size_t)(r0 + 8) * DM + col] = w1;
    }
}

// ---------------------------------------------------------------------------
extern "C" void kernel_launch(void* const* d_in, const int* in_sizes, int n_in,
                              void* d_out, int out_size)
{
    const float* hid = (const float*)d_in[0];
    const float* enc = (const float*)d_in[1];
    const float* rc  = (const float*)d_in[2];
    const float* rs  = (const float*)d_in[3];
    const float* Wq  = (const float*)d_in[4];
    const float* bq  = (const float*)d_in[5];
    const float* Wk  = (const float*)d_in[6];
    const float* bk  = (const float*)d_in[7];
    const float* Wv  = (const float*)d_in[8];
    const float* bv  = (const float*)d_in[9];
    const float* Waq = (const float*)d_in[10];
    const float* baq = (const float*)d_in[11];
    const float* Wak = (const float*)d_in[12];
    const float* bak = (const float*)d_in[13];
    const float* Wav = (const float*)d_in[14];
    const float* bav = (const float*)d_in[15];
    const float* Wo  = (const float*)d_in[16];
    const float* bo  = (const float*)d_in[17];
    const float* Wao = (const float*)d_in[18];
    const float* bao = (const float*)d_in[19];
    const float* gq  = (const float*)d_in[20];
    const float* gk  = (const float*)d_in[21];
    const float* gaq = (const float*)d_in[22];
    const float* gak = (const float*)d_in[23];
    float* out = (float*)d_out;

    cudaFuncSetAttribute(qkv_mma_kernel,
                         cudaFuncAttributeMaxDynamicSharedMemorySize, GEMM_SMEM_BYTES);
    cudaFuncSetAttribute(oproj_mma_kernel,
                         cudaFuncAttributeMaxDynamicSharedMemorySize, GEMM_SMEM_BYTES);
    cudaFuncSetAttribute(attn_mma_kernel,
                         cudaFuncAttributeMaxDynamicSharedMemorySize, ATTN_SMEM);

    qkv_mma_kernel<<<dim3(36, 20), 256, GEMM_SMEM_BYTES>>>(
        hid, enc, rc, rs, Wq, bq, Wk, bk, Wv, bv,
        Waq, baq, Wak, bak, Wav, bav, gq, gk, gaq, gak);

    attn_mma_kernel<<<dim3(20, 24), 256, ATTN_SMEM>>>();

    oproj_mma_kernel<<<dim3(12, 20), 256, GEMM_SMEM_BYTES>>>(Wo, bo, Wao, bao, out);
}